// round 14
// baseline (speedup 1.0000x reference)
#include <cuda_runtime.h>
#include <cuda_bf16.h>
#include <cuda_fp16.h>
#include <cstdint>
#include <math.h>

#define B_      64
#define S_      4096
#define A_      4
#define L_      64
#define D_      300
#define AL_     256
#define KPAD_   320         // padded K for bf16 B scratch
#define WINDOW_ 60
#define NW_     808
#define WPT_    32          // windows per warp task (pool)
#define NTASK_  26          // ceil(808/32)
#define NKT_    10          // GEMM K tiles of 32
#define PITCH_  80          // smem row pitch bytes (conflict-free ldmatrix)

// dynamic smem per CTA (64M x 256N, double-buffered K-tile 32)
#define OFF_A0_   0         // 64*80  = 5120
#define OFF_A1_   5120
#define OFF_B0_   10240     // 256*80 = 20480
#define OFF_B1_   30720
#define OFF_SQA_  51200     // 64 floats
#define OFF_SQB_  51456     // 256 floats
#define SMEM_GEMM 52480     // x2 CTAs = 104960 < 228KB

__device__ __half g_scores[(size_t)B_ * S_ * AL_];          // 134 MB fp16 scores
__device__ __nv_bfloat16 g_bbf[(size_t)B_ * AL_ * KPAD_];   // 10.5 MB bf16 B
__device__ float g_inv_a[B_ * AL_];
__device__ float g_taskmax[B_ * A_ * NTASK_];

__device__ __forceinline__ uint32_t smem_u32(const void* p) {
    uint32_t a;
    asm("{ .reg .u64 t; cvta.to.shared.u64 t, %1; cvt.u32.u64 %0, t; }" : "=r"(a) : "l"(p));
    return a;
}
__device__ __forceinline__ uint32_t pk2(float lo, float hi) {
    uint32_t r;
    asm("cvt.rn.bf16x2.f32 %0, %1, %2;" : "=r"(r) : "f"(hi), "f"(lo));
    return r;
}
__device__ __forceinline__ void ldm4(uint32_t* r, uint32_t addr) {
    asm volatile("ldmatrix.sync.aligned.m8n8.x4.shared.b16 {%0,%1,%2,%3}, [%4];"
                 : "=r"(r[0]), "=r"(r[1]), "=r"(r[2]), "=r"(r[3]) : "r"(addr));
}
__device__ __forceinline__ void mma_bf16(float* d, const uint32_t* a, const uint32_t* b) {
    asm volatile("mma.sync.aligned.m16n8k16.row.col.f32.bf16.bf16.f32 "
                 "{%0,%1,%2,%3}, {%4,%5,%6,%7}, {%8,%9}, {%0,%1,%2,%3};"
                 : "+f"(d[0]), "+f"(d[1]), "+f"(d[2]), "+f"(d[3])
                 : "r"(a[0]), "r"(a[1]), "r"(a[2]), "r"(a[3]), "r"(b[0]), "r"(b[1]));
}
__device__ __forceinline__ uint32_t hmul2(uint32_t a, uint32_t b) {
    uint32_t r;
    asm("mul.f16x2 %0, %1, %2;" : "=r"(r) : "r"(a), "r"(b));
    return r;
}
__device__ __forceinline__ uint32_t hmax2(uint32_t a, uint32_t b) {
    uint32_t r;
    asm("max.f16x2 %0, %1, %2;" : "=r"(r) : "r"(a), "r"(b));
    return r;
}

// ---------------------------------------------------------------------------
// B pre-convert: la fp32 [B][256][300] -> bf16 [B][256][320] (zero pad) + norms
// ---------------------------------------------------------------------------
__global__ __launch_bounds__(256) void bconv_kernel(const float* __restrict__ la) {
    const int row = blockIdx.x * 8 + (threadIdx.x >> 5);   // 0..16383
    const int lane = threadIdx.x & 31;
    const float* src = la + (size_t)row * D_;
    uint32_t* dst = (uint32_t*)(g_bbf + (size_t)row * KPAD_);
    float sq = 0.f;
#pragma unroll
    for (int i = 0; i < 5; i++) {
        const int e = (lane + 32 * i) * 2;
        float x0 = 0.f, x1 = 0.f;
        if (e < D_)     x0 = src[e];
        if (e + 1 < D_) x1 = src[e + 1];
        sq += x0 * x0 + x1 * x1;
        dst[lane + 32 * i] = pk2(x0, x1);
    }
#pragma unroll
    for (int o = 16; o; o >>= 1) sq += __shfl_xor_sync(0xffffffffu, sq, o);
    if (lane == 0) g_inv_a[row] = rsqrtf(sq + 1e-6f);
}

// ---------------------------------------------------------------------------
// GEMM: CTA 64M x 256N, 4 warps (1M x 4N), warp tile 64x64, K-tile 32,
// double-buffered (R8 per-warp instruction stream). 128 threads, 2 CTAs/SM
// -> two independent barrier domains for latency hiding.
// A: fp32 LDG + fused convert/norm. B: cp.async bf16. fp16 score stores.
// ---------------------------------------------------------------------------
__global__ __launch_bounds__(128, 2) void gemm_kernel(const float* __restrict__ ls) {
    extern __shared__ __align__(128) char sm[];
    float* sqA_sh = (float*)(sm + OFF_SQA_);
    float* sqB_sh = (float*)(sm + OFF_SQB_);

    const int tid  = threadIdx.x;          // 0..127
    const int lane = tid & 31, warp = tid >> 5;   // 4 warps
    const int b  = blockIdx.y;
    const int s0 = blockIdx.x * 64;
    const float* Ab = ls + ((size_t)b * S_ + s0) * D_;
    const char* Bbf = (const char*)g_bbf + (size_t)b * AL_ * (KPAD_ * 2);

    const int lrow = tid >> 1;      // 0..63 (A row)
    const int half = tid & 1;

    // warp tile 64x64: 1 warp over M, 4 over N
    const int wn = warp * 64;
    const int gid = lane >> 2, t4 = lane & 3;

    const int a_off0 = (lane & 15) * PITCH_ + ((lane >> 4) << 4);
    const int grp = lane >> 3;
    const int b_offj = (wn + (lane & 7) + ((grp >> 1) << 3)) * PITCH_ + ((grp & 1) << 4);

    const uint32_t asb[2] = {smem_u32(sm + OFF_A0_), smem_u32(sm + OFF_A1_)};
    const uint32_t bsb[2] = {smem_u32(sm + OFF_B0_), smem_u32(sm + OFF_B1_)};
    char* const Abuf[2] = {sm + OFF_A0_, sm + OFF_A1_};

    float acc[4][8][4];
#pragma unroll
    for (int mt = 0; mt < 4; mt++)
#pragma unroll
        for (int nt = 0; nt < 8; nt++)
#pragma unroll
            for (int i = 0; i < 4; i++) acc[mt][nt][i] = 0.f;

    float sqa = 0.f;
    float4 aR[4];

    auto ldgA = [&](int kt) {
        const int kbase = kt * 32 + half * 16;
        const float* pa = Ab + (size_t)lrow * D_ + kbase;
#pragma unroll
        for (int q = 0; q < 4; q++) {
            const bool v = (kbase + q * 4 + 4) <= D_;
            aR[q] = v ? *(const float4*)(pa + q * 4) : make_float4(0.f, 0.f, 0.f, 0.f);
        }
    };
    auto stashA = [&](int buf) {
        uint4 pk;
#pragma unroll
        for (int h = 0; h < 2; h++) {
            const float4 x0 = h ? aR[2] : aR[0];
            const float4 x1 = h ? aR[3] : aR[1];
            sqa += x0.x*x0.x + x0.y*x0.y + x0.z*x0.z + x0.w*x0.w
                 + x1.x*x1.x + x1.y*x1.y + x1.z*x1.z + x1.w*x1.w;
            pk.x = pk2(x0.x, x0.y); pk.y = pk2(x0.z, x0.w);
            pk.z = pk2(x1.x, x1.y); pk.w = pk2(x1.z, x1.w);
            *(uint4*)(Abuf[buf] + lrow * PITCH_ + half * 32 + h * 16) = pk;
        }
    };
    auto cpasyncB = [&](int kt, int buf) {
#pragma unroll
        for (int rr = 0; rr < 2; rr++) {
            const int row = tid + 128 * rr;       // 0..255
            const uint32_t dst = bsb[buf] + row * PITCH_;
            const char* src = Bbf + (size_t)row * (KPAD_ * 2) + kt * 64;
#pragma unroll
            for (int j = 0; j < 4; j++)
                asm volatile("cp.async.ca.shared.global [%0], [%1], 16;"
                             :: "r"(dst + j * 16), "l"(src + j * 16));
        }
    };

    cpasyncB(0, 0);
    asm volatile("cp.async.commit_group;");
    ldgA(0);
    stashA(0);
    asm volatile("cp.async.wait_group 0;");
    __syncthreads();

#pragma unroll 1
    for (int kt = 0; kt < NKT_; ++kt) {
        if (kt + 1 < NKT_) {
            ldgA(kt + 1);
            cpasyncB(kt + 1, (kt + 1) & 1);
            asm volatile("cp.async.commit_group;");
        }

        const int buf = kt & 1;
#pragma unroll
        for (int ks = 0; ks < 2; ks++) {
            uint32_t af[4][4];
#pragma unroll
            for (int mt = 0; mt < 4; mt++)
                ldm4(af[mt], asb[buf] + a_off0 + mt * 16 * PITCH_ + ks * 32);
            uint32_t bf[8][2];
#pragma unroll
            for (int j = 0; j < 4; j++) {
                uint32_t r[4];
                ldm4(r, bsb[buf] + b_offj + j * 16 * PITCH_ + ks * 32);
                bf[2*j][0] = r[0]; bf[2*j][1] = r[1];
                bf[2*j+1][0] = r[2]; bf[2*j+1][1] = r[3];
            }
#pragma unroll
            for (int nt = 0; nt < 8; nt++)
#pragma unroll
                for (int mt = 0; mt < 4; mt++)
                    mma_bf16(acc[mt][nt], af[mt], bf[nt]);
        }

        if (kt + 1 < NKT_) stashA((kt + 1) & 1);
        asm volatile("cp.async.wait_group 0;");
        __syncthreads();
    }

    sqa += __shfl_xor_sync(0xffffffffu, sqa, 1);
    if (half == 0) sqA_sh[lrow] = sqa;
    sqB_sh[tid]       = g_inv_a[b * AL_ + tid];
    sqB_sh[tid + 128] = g_inv_a[b * AL_ + tid + 128];
    __syncthreads();
    if (tid < 64) sqA_sh[tid] = rsqrtf(sqA_sh[tid] + 1e-6f);
    __syncthreads();

    __half* out = g_scores + ((size_t)b * S_ + s0) * AL_;
#pragma unroll
    for (int mt = 0; mt < 4; mt++) {
#pragma unroll
        for (int hh = 0; hh < 2; hh++) {
            const int r = mt * 16 + gid + hh * 8;         // 0..63
            const float is = sqA_sh[r];
#pragma unroll
            for (int nt = 0; nt < 8; nt++) {
                const int c = wn + nt * 8 + t4 * 2;
                const float vx = acc[mt][nt][hh * 2 + 0] * is * sqB_sh[c];
                const float vy = acc[mt][nt][hh * 2 + 1] * is * sqB_sh[c + 1];
                *(__half2*)(out + (size_t)r * AL_ + c) = __floats2half2_rn(vx, vy);
            }
        }
    }
}

// ---------------------------------------------------------------------------
// Pool: warp = 32 windows of one (b,a), fp16x2 math (R8 proven, unchanged).
// ---------------------------------------------------------------------------
__global__ __launch_bounds__(256) void pool_kernel(const float* __restrict__ wg) {
    __shared__ uint32_t gs2[WINDOW_];
    const int tid = threadIdx.x;
    if (tid < WINDOW_) {
        const __half h = __float2half_rn(wg[tid]);
        gs2[tid] = (uint32_t)__half_as_ushort(h) * 0x10001u;
    }
    __syncthreads();

    const int lane = tid & 31;
    const int task = blockIdx.x * 8 + (tid >> 5);   // 832*8 = 6656 = 256*26
    const int ba = task / NTASK_;
    const int chunk = task - ba * NTASK_;
    const int nw0 = chunk * WPT_;
    const int sbase = 5 * nw0;
    const __half* src = g_scores + (size_t)(ba >> 2) * S_ * AL_
                      + (size_t)(ba & 3) * L_ + 2 * lane;

    uint32_t acc[WPT_];
#pragma unroll
    for (int i = 0; i < WPT_; ++i) acc[i] = 0xFC00FC00u;   // -inf | -inf

#pragma unroll 1
    for (int p = 0; p < 5; ++p) {
        uint32_t g12[12];
#pragma unroll
        for (int q = 0; q < 12; ++q) g12[q] = gs2[5 * q + p];
#pragma unroll
        for (int r = 0; r < 43; ++r) {
            const int s = sbase + 5 * r + p;
            uint32_t v = 0u;
            if (s < S_) v = *(const uint32_t*)(src + (size_t)s * AL_);
#pragma unroll
            for (int q = 0; q < 12; ++q) {
                const int w = r - q;                 // compile-time
                if (w >= 0 && w < WPT_)
                    acc[w] = hmax2(acc[w], hmul2(g12[q], v));
            }
        }
    }

    float localmax = -INFINITY;
#pragma unroll
    for (int w = 0; w < WPT_; ++w) {
        const float2 f = __half22float2(*(__half2*)&acc[w]);
        float sum = f.x + f.y;
        float cnt = (f.x != 0.f ? 1.f : 0.f) + (f.y != 0.f ? 1.f : 0.f);
#pragma unroll
        for (int o = 16; o; o >>= 1) {
            sum += __shfl_xor_sync(0xffffffffu, sum, o);
            cnt += __shfl_xor_sync(0xffffffffu, cnt, o);
        }
        if (nw0 + w < NW_) localmax = fmaxf(localmax, sum / (cnt + 1e-5f));
    }
    if (lane == 0) g_taskmax[task] = localmax;
}

__global__ void final_kernel(const float* __restrict__ alpha, float* __restrict__ out) {
    const int i = threadIdx.x;  // 0..255 = b*4+a
    float mx = -INFINITY;
#pragma unroll
    for (int c = 0; c < NTASK_; ++c) mx = fmaxf(mx, g_taskmax[i * NTASK_ + c]);
    out[i] = mx * alpha[0];
}

// ---------------------------------------------------------------------------
extern "C" void kernel_launch(void* const* d_in, const int* in_sizes, int n_in,
                              void* d_out, int out_size) {
    const float* ls    = (const float*)d_in[0];
    const float* la    = (const float*)d_in[1];
    const float* alpha = (const float*)d_in[2];
    const float* wg    = (const float*)d_in[3];
    float* out = (float*)d_out;
    (void)in_sizes; (void)n_in; (void)out_size;

    bconv_kernel<<<(B_ * AL_) / 8, 256>>>(la);

    cudaFuncSetAttribute(gemm_kernel, cudaFuncAttributeMaxDynamicSharedMemorySize,
                         SMEM_GEMM);
    dim3 ggrid(S_ / 64, B_);   // (64, 64) -> 4096 CTAs
    gemm_kernel<<<ggrid, 128, SMEM_GEMM>>>(ls);

    pool_kernel<<<(B_ * A_ * NTASK_) / 8, 256>>>(wg);

    final_kernel<<<1, 256>>>(alpha, out);
}

// round 15
// speedup vs baseline: 1.3224x; 1.3224x over previous
#include <cuda_runtime.h>
#include <cuda_fp16.h>
#include <cstdint>
#include <math.h>

#define B_      64
#define S_      4096
#define A_      4
#define L_      64
#define D_      300
#define AL_     256
#define KPAD_   320         // padded K for fp16 B scratch
#define WINDOW_ 60
#define NW_     808
#define WPT_    32          // windows per warp task (pool)
#define NTASK_  26          // ceil(808/32)
#define NKT_    10          // GEMM K tiles of 32
#define PITCH_  80          // smem row pitch bytes (conflict-free ldmatrix)

// dynamic smem layout for GEMM (R8 proven shape)
#define OFF_A0_   0
#define OFF_A1_   10240
#define OFF_B0_   20480
#define OFF_B1_   40960
#define OFF_SQA_  61440
#define OFF_SQB_  61952     // 256 floats = 1024 B
#define SMEM_GEMM 62976

__device__ __half g_scores[(size_t)B_ * S_ * AL_];   // 134 MB fp16 scores
__device__ __half g_bhf[(size_t)B_ * AL_ * KPAD_];   // 10.5 MB fp16 B
__device__ float g_inv_a[B_ * AL_];
__device__ float g_taskmax[B_ * A_ * NTASK_];

__device__ __forceinline__ uint32_t smem_u32(const void* p) {
    uint32_t a;
    asm("{ .reg .u64 t; cvta.to.shared.u64 t, %1; cvt.u32.u64 %0, t; }" : "=r"(a) : "l"(p));
    return a;
}
__device__ __forceinline__ uint32_t pkh2(float lo, float hi) {
    const __half2 h = __floats2half2_rn(make_float2(lo, hi).x, make_float2(lo, hi).y);
    return *(const uint32_t*)&h;
}
__device__ __forceinline__ void ldm4(uint32_t* r, uint32_t addr) {
    asm volatile("ldmatrix.sync.aligned.m8n8.x4.shared.b16 {%0,%1,%2,%3}, [%4];"
                 : "=r"(r[0]), "=r"(r[1]), "=r"(r[2]), "=r"(r[3]) : "r"(addr));
}
// fp16 inputs, fp16 accumulators (packed half2 x2)
__device__ __forceinline__ void mma_f16acc(uint32_t* d, const uint32_t* a, const uint32_t* b) {
    asm volatile("mma.sync.aligned.m16n8k16.row.col.f16.f16.f16.f16 "
                 "{%0,%1}, {%2,%3,%4,%5}, {%6,%7}, {%0,%1};"
                 : "+r"(d[0]), "+r"(d[1])
                 : "r"(a[0]), "r"(a[1]), "r"(a[2]), "r"(a[3]), "r"(b[0]), "r"(b[1]));
}
__device__ __forceinline__ uint32_t hmul2(uint32_t a, uint32_t b) {
    uint32_t r;
    asm("mul.f16x2 %0, %1, %2;" : "=r"(r) : "r"(a), "r"(b));
    return r;
}
__device__ __forceinline__ uint32_t hmax2(uint32_t a, uint32_t b) {
    uint32_t r;
    asm("max.f16x2 %0, %1, %2;" : "=r"(r) : "r"(a), "r"(b));
    return r;
}

// ---------------------------------------------------------------------------
// B pre-convert: la fp32 [B][256][300] -> fp16 [B][256][320] (zero pad) + norms
// ---------------------------------------------------------------------------
__global__ __launch_bounds__(256) void bconv_kernel(const float* __restrict__ la) {
    const int row = blockIdx.x * 8 + (threadIdx.x >> 5);   // 0..16383
    const int lane = threadIdx.x & 31;
    const float* src = la + (size_t)row * D_;
    uint32_t* dst = (uint32_t*)(g_bhf + (size_t)row * KPAD_);
    float sq = 0.f;
#pragma unroll
    for (int i = 0; i < 5; i++) {
        const int e = (lane + 32 * i) * 2;
        float x0 = 0.f, x1 = 0.f;
        if (e < D_)     x0 = src[e];
        if (e + 1 < D_) x1 = src[e + 1];
        sq += x0 * x0 + x1 * x1;
        dst[lane + 32 * i] = pkh2(x0, x1);
    }
#pragma unroll
    for (int o = 16; o; o >>= 1) sq += __shfl_xor_sync(0xffffffffu, sq, o);
    if (lane == 0) g_inv_a[row] = rsqrtf(sq + 1e-6f);
}

// ---------------------------------------------------------------------------
// GEMM (R8 shape/order, fp16 HMMA): CTA 128M x 256N, 8 warps (2M x 4N),
// warp tile 64x64, K-tile 32, double-buffered. A: fp32 LDG + fused
// convert/norm (fp16). B: cp.async fp16. fp16-acc MMA. fp16 score stores.
// ---------------------------------------------------------------------------
__global__ __launch_bounds__(256) void gemm_kernel(const float* __restrict__ ls) {
    extern __shared__ __align__(128) char sm[];
    float* sqA_sh = (float*)(sm + OFF_SQA_);
    float* sqB_sh = (float*)(sm + OFF_SQB_);

    const int tid  = threadIdx.x;
    const int lane = tid & 31, warp = tid >> 5;
    const int b  = blockIdx.y;
    const int s0 = blockIdx.x * 128;
    const float* Ab = ls + ((size_t)b * S_ + s0) * D_;
    const char* Bhf = (const char*)g_bhf + (size_t)b * AL_ * (KPAD_ * 2);

    const int lrow = tid >> 1;      // 0..127
    const int half = tid & 1;

    const int wm = (warp & 1) * 64;
    const int wn = (warp >> 1) * 64;
    const int gid = lane >> 2, t4 = lane & 3;

    const int a_off0 = (wm + (lane & 15)) * PITCH_ + ((lane >> 4) << 4);
    const int grp = lane >> 3;
    const int b_offj = (wn + (lane & 7) + ((grp >> 1) << 3)) * PITCH_ + ((grp & 1) << 4);

    const uint32_t asb[2] = {smem_u32(sm + OFF_A0_), smem_u32(sm + OFF_A1_)};
    const uint32_t bsb[2] = {smem_u32(sm + OFF_B0_), smem_u32(sm + OFF_B1_)};
    char* const Abuf[2] = {sm + OFF_A0_, sm + OFF_A1_};

    uint32_t acc[4][8][2];          // fp16x2 accumulators
#pragma unroll
    for (int mt = 0; mt < 4; mt++)
#pragma unroll
        for (int nt = 0; nt < 8; nt++) {
            acc[mt][nt][0] = 0u;    // +0,+0
            acc[mt][nt][1] = 0u;
        }

    float sqa = 0.f;
    float4 aR[4];

    auto ldgA = [&](int kt) {
        const int kbase = kt * 32 + half * 16;
        const float* pa = Ab + (size_t)lrow * D_ + kbase;
#pragma unroll
        for (int q = 0; q < 4; q++) {
            const bool v = (kbase + q * 4 + 4) <= D_;
            aR[q] = v ? *(const float4*)(pa + q * 4) : make_float4(0.f, 0.f, 0.f, 0.f);
        }
    };
    auto stashA = [&](int buf) {
        uint4 pk;
#pragma unroll
        for (int h = 0; h < 2; h++) {
            const float4 x0 = h ? aR[2] : aR[0];
            const float4 x1 = h ? aR[3] : aR[1];
            sqa += x0.x*x0.x + x0.y*x0.y + x0.z*x0.z + x0.w*x0.w
                 + x1.x*x1.x + x1.y*x1.y + x1.z*x1.z + x1.w*x1.w;
            pk.x = pkh2(x0.x, x0.y); pk.y = pkh2(x0.z, x0.w);
            pk.z = pkh2(x1.x, x1.y); pk.w = pkh2(x1.z, x1.w);
            *(uint4*)(Abuf[buf] + lrow * PITCH_ + half * 32 + h * 16) = pk;
        }
    };
    auto cpasyncB = [&](int kt, int buf) {
#pragma unroll
        for (int rr = 0; rr < 2; rr++) {
            const int row = lrow + 128 * rr;
            const uint32_t dst = bsb[buf] + row * PITCH_ + half * 32;
            const char* src = Bhf + (size_t)row * (KPAD_ * 2) + kt * 64 + half * 32;
            asm volatile("cp.async.ca.shared.global [%0], [%1], 16;" :: "r"(dst), "l"(src));
            asm volatile("cp.async.ca.shared.global [%0], [%1], 16;"
                         :: "r"(dst + 16), "l"(src + 16));
        }
    };

    cpasyncB(0, 0);
    asm volatile("cp.async.commit_group;");
    ldgA(0);
    stashA(0);
    asm volatile("cp.async.wait_group 0;");
    __syncthreads();

#pragma unroll 1
    for (int kt = 0; kt < NKT_; ++kt) {
        if (kt + 1 < NKT_) {
            ldgA(kt + 1);
            cpasyncB(kt + 1, (kt + 1) & 1);
            asm volatile("cp.async.commit_group;");
        }

        const int buf = kt & 1;
#pragma unroll
        for (int ks = 0; ks < 2; ks++) {
            uint32_t af[4][4];
#pragma unroll
            for (int mt = 0; mt < 4; mt++)
                ldm4(af[mt], asb[buf] + a_off0 + mt * 16 * PITCH_ + ks * 32);
            uint32_t bf[8][2];
#pragma unroll
            for (int j = 0; j < 4; j++) {
                uint32_t r[4];
                ldm4(r, bsb[buf] + b_offj + j * 16 * PITCH_ + ks * 32);
                bf[2*j][0] = r[0]; bf[2*j][1] = r[1];
                bf[2*j+1][0] = r[2]; bf[2*j+1][1] = r[3];
            }
#pragma unroll
            for (int nt = 0; nt < 8; nt++)
#pragma unroll
                for (int mt = 0; mt < 4; mt++)
                    mma_f16acc(acc[mt][nt], af[mt], bf[nt]);
        }

        if (kt + 1 < NKT_) stashA((kt + 1) & 1);
        asm volatile("cp.async.wait_group 0;");
        __syncthreads();
    }

    sqa += __shfl_xor_sync(0xffffffffu, sqa, 1);
    if (half == 0) sqA_sh[lrow] = sqa;
    sqB_sh[tid] = g_inv_a[b * AL_ + tid];
    __syncthreads();
    if (tid < 128) sqA_sh[tid] = rsqrtf(sqA_sh[tid] + 1e-6f);
    __syncthreads();

    // epilogue: fp16-acc d-regs are (c, c+1) half2 pairs per row
    __half* out = g_scores + ((size_t)b * S_ + s0) * AL_;
#pragma unroll
    for (int mt = 0; mt < 4; mt++) {
#pragma unroll
        for (int hh = 0; hh < 2; hh++) {
            const int r = wm + mt * 16 + gid + hh * 8;
            const float is = sqA_sh[r];
#pragma unroll
            for (int nt = 0; nt < 8; nt++) {
                const int c = wn + nt * 8 + t4 * 2;
                const float2 f = __half22float2(*(const __half2*)&acc[mt][nt][hh]);
                const float vx = f.x * is * sqB_sh[c];
                const float vy = f.y * is * sqB_sh[c + 1];
                *(__half2*)(out + (size_t)r * AL_ + c) = __floats2half2_rn(vx, vy);
            }
        }
    }
}

// ---------------------------------------------------------------------------
// Pool: warp = 32 windows of one (b,a), fp16x2 math (R8 proven, unchanged).
// ---------------------------------------------------------------------------
__global__ __launch_bounds__(256) void pool_kernel(const float* __restrict__ wg) {
    __shared__ uint32_t gs2[WINDOW_];
    const int tid = threadIdx.x;
    if (tid < WINDOW_) {
        const __half h = __float2half_rn(wg[tid]);
        gs2[tid] = (uint32_t)__half_as_ushort(h) * 0x10001u;
    }
    __syncthreads();

    const int lane = tid & 31;
    const int task = blockIdx.x * 8 + (tid >> 5);   // 832*8 = 6656 = 256*26
    const int ba = task / NTASK_;
    const int chunk = task - ba * NTASK_;
    const int nw0 = chunk * WPT_;
    const int sbase = 5 * nw0;
    const __half* src = g_scores + (size_t)(ba >> 2) * S_ * AL_
                      + (size_t)(ba & 3) * L_ + 2 * lane;

    uint32_t acc[WPT_];
#pragma unroll
    for (int i = 0; i < WPT_; ++i) acc[i] = 0xFC00FC00u;   // -inf | -inf

#pragma unroll 1
    for (int p = 0; p < 5; ++p) {
        uint32_t g12[12];
#pragma unroll
        for (int q = 0; q < 12; ++q) g12[q] = gs2[5 * q + p];
#pragma unroll
        for (int r = 0; r < 43; ++r) {
            const int s = sbase + 5 * r + p;
            uint32_t v = 0u;
            if (s < S_) v = *(const uint32_t*)(src + (size_t)s * AL_);
#pragma unroll
            for (int q = 0; q < 12; ++q) {
                const int w = r - q;                 // compile-time
                if (w >= 0 && w < WPT_)
                    acc[w] = hmax2(acc[w], hmul2(g12[q], v));
            }
        }
    }

    float localmax = -INFINITY;
#pragma unroll
    for (int w = 0; w < WPT_; ++w) {
        const float2 f = __half22float2(*(__half2*)&acc[w]);
        float sum = f.x + f.y;
        float cnt = (f.x != 0.f ? 1.f : 0.f) + (f.y != 0.f ? 1.f : 0.f);
#pragma unroll
        for (int o = 16; o; o >>= 1) {
            sum += __shfl_xor_sync(0xffffffffu, sum, o);
            cnt += __shfl_xor_sync(0xffffffffu, cnt, o);
        }
        if (nw0 + w < NW_) localmax = fmaxf(localmax, sum / (cnt + 1e-5f));
    }
    if (lane == 0) g_taskmax[task] = localmax;
}

__global__ void final_kernel(const float* __restrict__ alpha, float* __restrict__ out) {
    const int i = threadIdx.x;  // 0..255 = b*4+a
    float mx = -INFINITY;
#pragma unroll
    for (int c = 0; c < NTASK_; ++c) mx = fmaxf(mx, g_taskmax[i * NTASK_ + c]);
    out[i] = mx * alpha[0];
}

// ---------------------------------------------------------------------------
extern "C" void kernel_launch(void* const* d_in, const int* in_sizes, int n_in,
                              void* d_out, int out_size) {
    const float* ls    = (const float*)d_in[0];
    const float* la    = (const float*)d_in[1];
    const float* alpha = (const float*)d_in[2];
    const float* wg    = (const float*)d_in[3];
    float* out = (float*)d_out;
    (void)in_sizes; (void)n_in; (void)out_size;

    bconv_kernel<<<(B_ * AL_) / 8, 256>>>(la);

    cudaFuncSetAttribute(gemm_kernel, cudaFuncAttributeMaxDynamicSharedMemorySize,
                         SMEM_GEMM);
    dim3 ggrid(S_ / 128, B_);   // (32, 64) -> 2048 CTAs
    gemm_kernel<<<ggrid, 256, SMEM_GEMM>>>(ls);

    pool_kernel<<<(B_ * A_ * NTASK_) / 8, 256>>>(wg);

    final_kernel<<<1, 256>>>(alpha, out);
}

// round 16
// speedup vs baseline: 1.3383x; 1.0121x over previous
#include <cuda_runtime.h>
#include <cuda_fp16.h>
#include <cstdint>
#include <math.h>

#define B_      64
#define S_      4096
#define A_      4
#define L_      64
#define D_      300
#define AL_     256
#define KPAD_   320         // padded K for fp16 B scratch
#define WINDOW_ 60
#define NW_     808
#define WPT_    64          // windows per warp task (pool)
#define NTASK_  13          // ceil(808/64)
#define NRP_    75          // rows per phase in a task: r = 0..74 (5*74+4 = 374)
#define NKT_    10          // GEMM K tiles of 32
#define PITCH_  80          // smem row pitch bytes (conflict-free ldmatrix)

// dynamic smem layout for GEMM (R8/R15 proven shape)
#define OFF_A0_   0
#define OFF_A1_   10240
#define OFF_B0_   20480
#define OFF_B1_   40960
#define OFF_SQA_  61440
#define OFF_SQB_  61952     // 256 floats = 1024 B
#define SMEM_GEMM 62976

__device__ __half g_scores[(size_t)B_ * S_ * AL_];   // 134 MB fp16 scores
__device__ __half g_bhf[(size_t)B_ * AL_ * KPAD_];   // 10.5 MB fp16 B
__device__ float g_inv_a[B_ * AL_];
__device__ float g_taskmax[B_ * A_ * NTASK_];

__device__ __forceinline__ uint32_t smem_u32(const void* p) {
    uint32_t a;
    asm("{ .reg .u64 t; cvta.to.shared.u64 t, %1; cvt.u32.u64 %0, t; }" : "=r"(a) : "l"(p));
    return a;
}
__device__ __forceinline__ uint32_t pkh2(float lo, float hi) {
    const __half2 h = __floats2half2_rn(lo, hi);
    return *(const uint32_t*)&h;
}
__device__ __forceinline__ void ldm4(uint32_t* r, uint32_t addr) {
    asm volatile("ldmatrix.sync.aligned.m8n8.x4.shared.b16 {%0,%1,%2,%3}, [%4];"
                 : "=r"(r[0]), "=r"(r[1]), "=r"(r[2]), "=r"(r[3]) : "r"(addr));
}
// fp16 inputs, fp16 accumulators (packed half2 x2)
__device__ __forceinline__ void mma_f16acc(uint32_t* d, const uint32_t* a, const uint32_t* b) {
    asm volatile("mma.sync.aligned.m16n8k16.row.col.f16.f16.f16.f16 "
                 "{%0,%1}, {%2,%3,%4,%5}, {%6,%7}, {%0,%1};"
                 : "+r"(d[0]), "+r"(d[1])
                 : "r"(a[0]), "r"(a[1]), "r"(a[2]), "r"(a[3]), "r"(b[0]), "r"(b[1]));
}
__device__ __forceinline__ uint32_t hmul2(uint32_t a, uint32_t b) {
    uint32_t r;
    asm("mul.f16x2 %0, %1, %2;" : "=r"(r) : "r"(a), "r"(b));
    return r;
}
__device__ __forceinline__ uint32_t hmax2(uint32_t a, uint32_t b) {
    uint32_t r;
    asm("max.f16x2 %0, %1, %2;" : "=r"(r) : "r"(a), "r"(b));
    return r;
}

// ---------------------------------------------------------------------------
// B pre-convert: la fp32 [B][256][300] -> fp16 [B][256][320] (zero pad) + norms
// ---------------------------------------------------------------------------
__global__ __launch_bounds__(256) void bconv_kernel(const float* __restrict__ la) {
    const int row = blockIdx.x * 8 + (threadIdx.x >> 5);   // 0..16383
    const int lane = threadIdx.x & 31;
    const float* src = la + (size_t)row * D_;
    uint32_t* dst = (uint32_t*)(g_bhf + (size_t)row * KPAD_);
    float sq = 0.f;
#pragma unroll
    for (int i = 0; i < 5; i++) {
        const int e = (lane + 32 * i) * 2;
        float x0 = 0.f, x1 = 0.f;
        if (e < D_)     x0 = src[e];
        if (e + 1 < D_) x1 = src[e + 1];
        sq += x0 * x0 + x1 * x1;
        dst[lane + 32 * i] = pkh2(x0, x1);
    }
#pragma unroll
    for (int o = 16; o; o >>= 1) sq += __shfl_xor_sync(0xffffffffu, sq, o);
    if (lane == 0) g_inv_a[row] = rsqrtf(sq + 1e-6f);
}

// ---------------------------------------------------------------------------
// GEMM (frozen R15): CTA 128M x 256N, 8 warps (2M x 4N), warp tile 64x64,
// K-tile 32, double-buffered. A: fp32 LDG + fused convert/norm (fp16).
// B: cp.async fp16. fp16-acc MMA. fp16 score stores.
// ---------------------------------------------------------------------------
__global__ __launch_bounds__(256) void gemm_kernel(const float* __restrict__ ls) {
    extern __shared__ __align__(128) char sm[];
    float* sqA_sh = (float*)(sm + OFF_SQA_);
    float* sqB_sh = (float*)(sm + OFF_SQB_);

    const int tid  = threadIdx.x;
    const int lane = tid & 31, warp = tid >> 5;
    const int b  = blockIdx.y;
    const int s0 = blockIdx.x * 128;
    const float* Ab = ls + ((size_t)b * S_ + s0) * D_;
    const char* Bhf = (const char*)g_bhf + (size_t)b * AL_ * (KPAD_ * 2);

    const int lrow = tid >> 1;      // 0..127
    const int half = tid & 1;

    const int wm = (warp & 1) * 64;
    const int wn = (warp >> 1) * 64;
    const int gid = lane >> 2, t4 = lane & 3;

    const int a_off0 = (wm + (lane & 15)) * PITCH_ + ((lane >> 4) << 4);
    const int grp = lane >> 3;
    const int b_offj = (wn + (lane & 7) + ((grp >> 1) << 3)) * PITCH_ + ((grp & 1) << 4);

    const uint32_t asb[2] = {smem_u32(sm + OFF_A0_), smem_u32(sm + OFF_A1_)};
    const uint32_t bsb[2] = {smem_u32(sm + OFF_B0_), smem_u32(sm + OFF_B1_)};
    char* const Abuf[2] = {sm + OFF_A0_, sm + OFF_A1_};

    uint32_t acc[4][8][2];          // fp16x2 accumulators
#pragma unroll
    for (int mt = 0; mt < 4; mt++)
#pragma unroll
        for (int nt = 0; nt < 8; nt++) {
            acc[mt][nt][0] = 0u;
            acc[mt][nt][1] = 0u;
        }

    float sqa = 0.f;
    float4 aR[4];

    auto ldgA = [&](int kt) {
        const int kbase = kt * 32 + half * 16;
        const float* pa = Ab + (size_t)lrow * D_ + kbase;
#pragma unroll
        for (int q = 0; q < 4; q++) {
            const bool v = (kbase + q * 4 + 4) <= D_;
            aR[q] = v ? *(const float4*)(pa + q * 4) : make_float4(0.f, 0.f, 0.f, 0.f);
        }
    };
    auto stashA = [&](int buf) {
        uint4 pk;
#pragma unroll
        for (int h = 0; h < 2; h++) {
            const float4 x0 = h ? aR[2] : aR[0];
            const float4 x1 = h ? aR[3] : aR[1];
            sqa += x0.x*x0.x + x0.y*x0.y + x0.z*x0.z + x0.w*x0.w
                 + x1.x*x1.x + x1.y*x1.y + x1.z*x1.z + x1.w*x1.w;
            pk.x = pkh2(x0.x, x0.y); pk.y = pkh2(x0.z, x0.w);
            pk.z = pkh2(x1.x, x1.y); pk.w = pkh2(x1.z, x1.w);
            *(uint4*)(Abuf[buf] + lrow * PITCH_ + half * 32 + h * 16) = pk;
        }
    };
    auto cpasyncB = [&](int kt, int buf) {
#pragma unroll
        for (int rr = 0; rr < 2; rr++) {
            const int row = lrow + 128 * rr;
            const uint32_t dst = bsb[buf] + row * PITCH_ + half * 32;
            const char* src = Bhf + (size_t)row * (KPAD_ * 2) + kt * 64 + half * 32;
            asm volatile("cp.async.ca.shared.global [%0], [%1], 16;" :: "r"(dst), "l"(src));
            asm volatile("cp.async.ca.shared.global [%0], [%1], 16;"
                         :: "r"(dst + 16), "l"(src + 16));
        }
    };

    cpasyncB(0, 0);
    asm volatile("cp.async.commit_group;");
    ldgA(0);
    stashA(0);
    asm volatile("cp.async.wait_group 0;");
    __syncthreads();

#pragma unroll 1
    for (int kt = 0; kt < NKT_; ++kt) {
        if (kt + 1 < NKT_) {
            ldgA(kt + 1);
            cpasyncB(kt + 1, (kt + 1) & 1);
            asm volatile("cp.async.commit_group;");
        }

        const int buf = kt & 1;
#pragma unroll
        for (int ks = 0; ks < 2; ks++) {
            uint32_t af[4][4];
#pragma unroll
            for (int mt = 0; mt < 4; mt++)
                ldm4(af[mt], asb[buf] + a_off0 + mt * 16 * PITCH_ + ks * 32);
            uint32_t bf[8][2];
#pragma unroll
            for (int j = 0; j < 4; j++) {
                uint32_t r[4];
                ldm4(r, bsb[buf] + b_offj + j * 16 * PITCH_ + ks * 32);
                bf[2*j][0] = r[0]; bf[2*j][1] = r[1];
                bf[2*j+1][0] = r[2]; bf[2*j+1][1] = r[3];
            }
#pragma unroll
            for (int nt = 0; nt < 8; nt++)
#pragma unroll
                for (int mt = 0; mt < 4; mt++)
                    mma_f16acc(acc[mt][nt], af[mt], bf[nt]);
        }

        if (kt + 1 < NKT_) stashA((kt + 1) & 1);
        asm volatile("cp.async.wait_group 0;");
        __syncthreads();
    }

    sqa += __shfl_xor_sync(0xffffffffu, sqa, 1);
    if (half == 0) sqA_sh[lrow] = sqa;
    sqB_sh[tid] = g_inv_a[b * AL_ + tid];
    __syncthreads();
    if (tid < 128) sqA_sh[tid] = rsqrtf(sqA_sh[tid] + 1e-6f);
    __syncthreads();

    __half* out = g_scores + ((size_t)b * S_ + s0) * AL_;
#pragma unroll
    for (int mt = 0; mt < 4; mt++) {
#pragma unroll
        for (int hh = 0; hh < 2; hh++) {
            const int r = wm + mt * 16 + gid + hh * 8;
            const float is = sqA_sh[r];
#pragma unroll
            for (int nt = 0; nt < 8; nt++) {
                const int c = wn + nt * 8 + t4 * 2;
                const float2 f = __half22float2(*(const __half2*)&acc[mt][nt][hh]);
                const float vx = f.x * is * sqB_sh[c];
                const float vy = f.y * is * sqB_sh[c + 1];
                *(__half2*)(out + (size_t)r * AL_ + c) = __floats2half2_rn(vx, vy);
            }
        }
    }
}

// ---------------------------------------------------------------------------
// Pool: warp = 64 windows of one (b,a), fp16x2 math. Halo redundancy 17%
// (vs 34% at WPT 32). Guard-free fast path for chunks 0..11; chunk 12 guarded.
// ---------------------------------------------------------------------------
template <bool GUARD>
__device__ __forceinline__ float pool_body(const __half* src, const uint32_t* gs2,
                                           int sbase, int nw0) {
    uint32_t acc[WPT_];
#pragma unroll
    for (int i = 0; i < WPT_; ++i) acc[i] = 0xFC00FC00u;   // -inf | -inf

#pragma unroll 1
    for (int p = 0; p < 5; ++p) {
        uint32_t g12[12];
#pragma unroll
        for (int q = 0; q < 12; ++q) g12[q] = gs2[5 * q + p];
#pragma unroll
        for (int r = 0; r < NRP_; ++r) {
            const int s = sbase + 5 * r + p;
            uint32_t v;
            if (GUARD) {
                v = 0u;
                if (s < S_) v = *(const uint32_t*)(src + (size_t)s * AL_);
            } else {
                v = *(const uint32_t*)(src + (size_t)s * AL_);
            }
#pragma unroll
            for (int q = 0; q < 12; ++q) {
                const int w = r - q;                 // compile-time
                if (w >= 0 && w < WPT_)
                    acc[w] = hmax2(acc[w], hmul2(g12[q], v));
            }
        }
    }

    float localmax = -INFINITY;
#pragma unroll
    for (int w = 0; w < WPT_; ++w) {
        const float2 f = __half22float2(*(__half2*)&acc[w]);
        float sum = f.x + f.y;
        float cnt = (f.x != 0.f ? 1.f : 0.f) + (f.y != 0.f ? 1.f : 0.f);
#pragma unroll
        for (int o = 16; o; o >>= 1) {
            sum += __shfl_xor_sync(0xffffffffu, sum, o);
            cnt += __shfl_xor_sync(0xffffffffu, cnt, o);
        }
        const float avg = sum / (cnt + 1e-5f);
        if (!GUARD || (nw0 + w < NW_)) localmax = fmaxf(localmax, avg);
    }
    return localmax;
}

__global__ __launch_bounds__(256) void pool_kernel(const float* __restrict__ wg) {
    __shared__ uint32_t gs2[WINDOW_];
    const int tid = threadIdx.x;
    if (tid < WINDOW_) {
        const __half h = __float2half_rn(wg[tid]);
        gs2[tid] = (uint32_t)__half_as_ushort(h) * 0x10001u;
    }
    __syncthreads();

    const int lane = tid & 31;
    const int task = blockIdx.x * 8 + (tid >> 5);   // 416*8 = 3328 = 256*13
    const int ba = task / NTASK_;
    const int chunk = task - ba * NTASK_;
    const int nw0 = chunk * WPT_;
    const int sbase = 5 * nw0;
    const __half* src = g_scores + (size_t)(ba >> 2) * S_ * AL_
                      + (size_t)(ba & 3) * L_ + 2 * lane;

    float localmax;
    if (chunk < NTASK_ - 1) localmax = pool_body<false>(src, gs2, sbase, nw0);
    else                    localmax = pool_body<true >(src, gs2, sbase, nw0);

    if (lane == 0) g_taskmax[task] = localmax;
}

__global__ void final_kernel(const float* __restrict__ alpha, float* __restrict__ out) {
    const int i = threadIdx.x;  // 0..255 = b*4+a
    float mx = -INFINITY;
#pragma unroll
    for (int c = 0; c < NTASK_; ++c) mx = fmaxf(mx, g_taskmax[i * NTASK_ + c]);
    out[i] = mx * alpha[0];
}

// ---------------------------------------------------------------------------
extern "C" void kernel_launch(void* const* d_in, const int* in_sizes, int n_in,
                              void* d_out, int out_size) {
    const float* ls    = (const float*)d_in[0];
    const float* la    = (const float*)d_in[1];
    const float* alpha = (const float*)d_in[2];
    const float* wg    = (const float*)d_in[3];
    float* out = (float*)d_out;
    (void)in_sizes; (void)n_in; (void)out_size;

    bconv_kernel<<<(B_ * AL_) / 8, 256>>>(la);

    cudaFuncSetAttribute(gemm_kernel, cudaFuncAttributeMaxDynamicSharedMemorySize,
                         SMEM_GEMM);
    dim3 ggrid(S_ / 128, B_);   // (32, 64) -> 2048 CTAs
    gemm_kernel<<<ggrid, 256, SMEM_GEMM>>>(ls);

    pool_kernel<<<(B_ * A_ * NTASK_) / 8, 256>>>(wg);

    final_kernel<<<1, 256>>>(alpha, out);
}

// round 17
// speedup vs baseline: 1.3476x; 1.0069x over previous
#include <cuda_runtime.h>
#include <cuda_fp16.h>
#include <cstdint>
#include <math.h>

#define B_      64
#define S_      4096
#define A_      4
#define L_      64
#define D_      300
#define AL_     256
#define KPAD_   320         // padded K for fp16 B scratch
#define WINDOW_ 60
#define NW_     808
#define WPT_    64          // windows per warp task (pool)
#define NTASK_  13          // ceil(808/64)
#define NRP_    75          // rows per phase in a task: r = 0..74 (5*74+4 = 374)
#define NKT_    10          // GEMM K tiles of 32
#define PITCH_  80          // smem row pitch bytes (conflict-free ldmatrix)

// dynamic smem layout for GEMM (R8/R15 proven shape)
#define OFF_A0_   0
#define OFF_A1_   10240
#define OFF_B0_   20480
#define OFF_B1_   40960
#define OFF_SQA_  61440
#define OFF_SQB_  61952     // 256 floats = 1024 B
#define SMEM_GEMM 62976

__device__ __half g_scores[(size_t)B_ * S_ * AL_];   // 134 MB fp16 scores
__device__ __half g_bhf[(size_t)B_ * AL_ * KPAD_];   // 10.5 MB fp16 B
__device__ float g_inv_a[B_ * AL_];
__device__ float g_taskmax[B_ * A_ * NTASK_];

__device__ __forceinline__ uint32_t smem_u32(const void* p) {
    uint32_t a;
    asm("{ .reg .u64 t; cvta.to.shared.u64 t, %1; cvt.u32.u64 %0, t; }" : "=r"(a) : "l"(p));
    return a;
}
__device__ __forceinline__ uint32_t pkh2(float lo, float hi) {
    const __half2 h = __floats2half2_rn(lo, hi);
    return *(const uint32_t*)&h;
}
__device__ __forceinline__ void ldm4(uint32_t* r, uint32_t addr) {
    asm volatile("ldmatrix.sync.aligned.m8n8.x4.shared.b16 {%0,%1,%2,%3}, [%4];"
                 : "=r"(r[0]), "=r"(r[1]), "=r"(r[2]), "=r"(r[3]) : "r"(addr));
}
// fp16 inputs, fp16 accumulators (packed half2 x2)
__device__ __forceinline__ void mma_f16acc(uint32_t* d, const uint32_t* a, const uint32_t* b) {
    asm volatile("mma.sync.aligned.m16n8k16.row.col.f16.f16.f16.f16 "
                 "{%0,%1}, {%2,%3,%4,%5}, {%6,%7}, {%0,%1};"
                 : "+r"(d[0]), "+r"(d[1])
                 : "r"(a[0]), "r"(a[1]), "r"(a[2]), "r"(a[3]), "r"(b[0]), "r"(b[1]));
}
__device__ __forceinline__ uint32_t hmul2(uint32_t a, uint32_t b) {
    uint32_t r;
    asm("mul.f16x2 %0, %1, %2;" : "=r"(r) : "r"(a), "r"(b));
    return r;
}
__device__ __forceinline__ uint32_t hmax2(uint32_t a, uint32_t b) {
    uint32_t r;
    asm("max.f16x2 %0, %1, %2;" : "=r"(r) : "r"(a), "r"(b));
    return r;
}

// ---------------------------------------------------------------------------
// B pre-convert: la fp32 [B][256][300] -> fp16 [B][256][320] (zero pad) + norms
// ---------------------------------------------------------------------------
__global__ __launch_bounds__(256) void bconv_kernel(const float* __restrict__ la) {
    const int row = blockIdx.x * 8 + (threadIdx.x >> 5);   // 0..16383
    const int lane = threadIdx.x & 31;
    const float* src = la + (size_t)row * D_;
    uint32_t* dst = (uint32_t*)(g_bhf + (size_t)row * KPAD_);
    float sq = 0.f;
#pragma unroll
    for (int i = 0; i < 5; i++) {
        const int e = (lane + 32 * i) * 2;
        float x0 = 0.f, x1 = 0.f;
        if (e < D_)     x0 = src[e];
        if (e + 1 < D_) x1 = src[e + 1];
        sq += x0 * x0 + x1 * x1;
        dst[lane + 32 * i] = pkh2(x0, x1);
    }
#pragma unroll
    for (int o = 16; o; o >>= 1) sq += __shfl_xor_sync(0xffffffffu, sq, o);
    if (lane == 0) g_inv_a[row] = rsqrtf(sq + 1e-6f);
}

// ---------------------------------------------------------------------------
// GEMM (R15 instruction stream; NEW: 2 CTAs/SM via launch bounds).
// CTA 128M x 256N, 8 warps (2M x 4N), warp tile 64x64, K-tile 32,
// double-buffered. A: fp32 LDG + fused convert/norm (fp16). B: cp.async fp16.
// fp16-acc MMA. fp16 score stores.
// ---------------------------------------------------------------------------
__global__ __launch_bounds__(256, 2) void gemm_kernel(const float* __restrict__ ls) {
    extern __shared__ __align__(128) char sm[];
    float* sqA_sh = (float*)(sm + OFF_SQA_);
    float* sqB_sh = (float*)(sm + OFF_SQB_);

    const int tid  = threadIdx.x;
    const int lane = tid & 31, warp = tid >> 5;
    const int b  = blockIdx.y;
    const int s0 = blockIdx.x * 128;
    const float* Ab = ls + ((size_t)b * S_ + s0) * D_;
    const char* Bhf = (const char*)g_bhf + (size_t)b * AL_ * (KPAD_ * 2);

    const int lrow = tid >> 1;      // 0..127
    const int half = tid & 1;

    const int wm = (warp & 1) * 64;
    const int wn = (warp >> 1) * 64;
    const int gid = lane >> 2, t4 = lane & 3;

    const int a_off0 = (wm + (lane & 15)) * PITCH_ + ((lane >> 4) << 4);
    const int grp = lane >> 3;
    const int b_offj = (wn + (lane & 7) + ((grp >> 1) << 3)) * PITCH_ + ((grp & 1) << 4);

    const uint32_t asb[2] = {smem_u32(sm + OFF_A0_), smem_u32(sm + OFF_A1_)};
    const uint32_t bsb[2] = {smem_u32(sm + OFF_B0_), smem_u32(sm + OFF_B1_)};
    char* const Abuf[2] = {sm + OFF_A0_, sm + OFF_A1_};

    uint32_t acc[4][8][2];          // fp16x2 accumulators
#pragma unroll
    for (int mt = 0; mt < 4; mt++)
#pragma unroll
        for (int nt = 0; nt < 8; nt++) {
            acc[mt][nt][0] = 0u;
            acc[mt][nt][1] = 0u;
        }

    float sqa = 0.f;
    float4 aR[4];

    auto ldgA = [&](int kt) {
        const int kbase = kt * 32 + half * 16;
        const float* pa = Ab + (size_t)lrow * D_ + kbase;
#pragma unroll
        for (int q = 0; q < 4; q++) {
            const bool v = (kbase + q * 4 + 4) <= D_;
            aR[q] = v ? *(const float4*)(pa + q * 4) : make_float4(0.f, 0.f, 0.f, 0.f);
        }
    };
    auto stashA = [&](int buf) {
        uint4 pk;
#pragma unroll
        for (int h = 0; h < 2; h++) {
            const float4 x0 = h ? aR[2] : aR[0];
            const float4 x1 = h ? aR[3] : aR[1];
            sqa += x0.x*x0.x + x0.y*x0.y + x0.z*x0.z + x0.w*x0.w
                 + x1.x*x1.x + x1.y*x1.y + x1.z*x1.z + x1.w*x1.w;
            pk.x = pkh2(x0.x, x0.y); pk.y = pkh2(x0.z, x0.w);
            pk.z = pkh2(x1.x, x1.y); pk.w = pkh2(x1.z, x1.w);
            *(uint4*)(Abuf[buf] + lrow * PITCH_ + half * 32 + h * 16) = pk;
        }
    };
    auto cpasyncB = [&](int kt, int buf) {
#pragma unroll
        for (int rr = 0; rr < 2; rr++) {
            const int row = lrow + 128 * rr;
            const uint32_t dst = bsb[buf] + row * PITCH_ + half * 32;
            const char* src = Bhf + (size_t)row * (KPAD_ * 2) + kt * 64 + half * 32;
            asm volatile("cp.async.ca.shared.global [%0], [%1], 16;" :: "r"(dst), "l"(src));
            asm volatile("cp.async.ca.shared.global [%0], [%1], 16;"
                         :: "r"(dst + 16), "l"(src + 16));
        }
    };

    cpasyncB(0, 0);
    asm volatile("cp.async.commit_group;");
    ldgA(0);
    stashA(0);
    asm volatile("cp.async.wait_group 0;");
    __syncthreads();

#pragma unroll 1
    for (int kt = 0; kt < NKT_; ++kt) {
        if (kt + 1 < NKT_) {
            ldgA(kt + 1);
            cpasyncB(kt + 1, (kt + 1) & 1);
            asm volatile("cp.async.commit_group;");
        }

        const int buf = kt & 1;
#pragma unroll
        for (int ks = 0; ks < 2; ks++) {
            uint32_t af[4][4];
#pragma unroll
            for (int mt = 0; mt < 4; mt++)
                ldm4(af[mt], asb[buf] + a_off0 + mt * 16 * PITCH_ + ks * 32);
            uint32_t bf[8][2];
#pragma unroll
            for (int j = 0; j < 4; j++) {
                uint32_t r[4];
                ldm4(r, bsb[buf] + b_offj + j * 16 * PITCH_ + ks * 32);
                bf[2*j][0] = r[0]; bf[2*j][1] = r[1];
                bf[2*j+1][0] = r[2]; bf[2*j+1][1] = r[3];
            }
#pragma unroll
            for (int nt = 0; nt < 8; nt++)
#pragma unroll
                for (int mt = 0; mt < 4; mt++)
                    mma_f16acc(acc[mt][nt], af[mt], bf[nt]);
        }

        if (kt + 1 < NKT_) stashA((kt + 1) & 1);
        asm volatile("cp.async.wait_group 0;");
        __syncthreads();
    }

    sqa += __shfl_xor_sync(0xffffffffu, sqa, 1);
    if (half == 0) sqA_sh[lrow] = sqa;
    sqB_sh[tid] = g_inv_a[b * AL_ + tid];
    __syncthreads();
    if (tid < 128) sqA_sh[tid] = rsqrtf(sqA_sh[tid] + 1e-6f);
    __syncthreads();

    __half* out = g_scores + ((size_t)b * S_ + s0) * AL_;
#pragma unroll
    for (int mt = 0; mt < 4; mt++) {
#pragma unroll
        for (int hh = 0; hh < 2; hh++) {
            const int r = wm + mt * 16 + gid + hh * 8;
            const float is = sqA_sh[r];
#pragma unroll
            for (int nt = 0; nt < 8; nt++) {
                const int c = wn + nt * 8 + t4 * 2;
                const float2 f = __half22float2(*(const __half2*)&acc[mt][nt][hh]);
                const float vx = f.x * is * sqB_sh[c];
                const float vy = f.y * is * sqB_sh[c + 1];
                *(__half2*)(out + (size_t)r * AL_ + c) = __floats2half2_rn(vx, vy);
            }
        }
    }
}

// ---------------------------------------------------------------------------
// Pool: warp = 64 windows of one (b,a), fp16x2 math. Guard-free fast path for
// chunks 0..11; chunk 12 guarded. (R16 proven, unchanged.)
// ---------------------------------------------------------------------------
template <bool GUARD>
__device__ __forceinline__ float pool_body(const __half* src, const uint32_t* gs2,
                                           int sbase, int nw0) {
    uint32_t acc[WPT_];
#pragma unroll
    for (int i = 0; i < WPT_; ++i) acc[i] = 0xFC00FC00u;   // -inf | -inf

#pragma unroll 1
    for (int p = 0; p < 5; ++p) {
        uint32_t g12[12];
#pragma unroll
        for (int q = 0; q < 12; ++q) g12[q] = gs2[5 * q + p];
#pragma unroll
        for (int r = 0; r < NRP_; ++r) {
            const int s = sbase + 5 * r + p;
            uint32_t v;
            if (GUARD) {
                v = 0u;
                if (s < S_) v = *(const uint32_t*)(src + (size_t)s * AL_);
            } else {
                v = *(const uint32_t*)(src + (size_t)s * AL_);
            }
#pragma unroll
            for (int q = 0; q < 12; ++q) {
                const int w = r - q;                 // compile-time
                if (w >= 0 && w < WPT_)
                    acc[w] = hmax2(acc[w], hmul2(g12[q], v));
            }
        }
    }

    float localmax = -INFINITY;
#pragma unroll
    for (int w = 0; w < WPT_; ++w) {
        const float2 f = __half22float2(*(__half2*)&acc[w]);
        float sum = f.x + f.y;
        float cnt = (f.x != 0.f ? 1.f : 0.f) + (f.y != 0.f ? 1.f : 0.f);
#pragma unroll
        for (int o = 16; o; o >>= 1) {
            sum += __shfl_xor_sync(0xffffffffu, sum, o);
            cnt += __shfl_xor_sync(0xffffffffu, cnt, o);
        }
        const float avg = sum / (cnt + 1e-5f);
        if (!GUARD || (nw0 + w < NW_)) localmax = fmaxf(localmax, avg);
    }
    return localmax;
}

__global__ __launch_bounds__(256) void pool_kernel(const float* __restrict__ wg) {
    __shared__ uint32_t gs2[WINDOW_];
    const int tid = threadIdx.x;
    if (tid < WINDOW_) {
        const __half h = __float2half_rn(wg[tid]);
        gs2[tid] = (uint32_t)__half_as_ushort(h) * 0x10001u;
    }
    __syncthreads();

    const int lane = tid & 31;
    const int task = blockIdx.x * 8 + (tid >> 5);   // 416*8 = 3328 = 256*13
    const int ba = task / NTASK_;
    const int chunk = task - ba * NTASK_;
    const int nw0 = chunk * WPT_;
    const int sbase = 5 * nw0;
    const __half* src = g_scores + (size_t)(ba >> 2) * S_ * AL_
                      + (size_t)(ba & 3) * L_ + 2 * lane;

    float localmax;
    if (chunk < NTASK_ - 1) localmax = pool_body<false>(src, gs2, sbase, nw0);
    else                    localmax = pool_body<true >(src, gs2, sbase, nw0);

    if (lane == 0) g_taskmax[task] = localmax;
}

__global__ void final_kernel(const float* __restrict__ alpha, float* __restrict__ out) {
    const int i = threadIdx.x;  // 0..255 = b*4+a
    float mx = -INFINITY;
#pragma unroll
    for (int c = 0; c < NTASK_; ++c) mx = fmaxf(mx, g_taskmax[i * NTASK_ + c]);
    out[i] = mx * alpha[0];
}

// ---------------------------------------------------------------------------
extern "C" void kernel_launch(void* const* d_in, const int* in_sizes, int n_in,
                              void* d_out, int out_size) {
    const float* ls    = (const float*)d_in[0];
    const float* la    = (const float*)d_in[1];
    const float* alpha = (const float*)d_in[2];
    const float* wg    = (const float*)d_in[3];
    float* out = (float*)d_out;
    (void)in_sizes; (void)n_in; (void)out_size;

    bconv_kernel<<<(B_ * AL_) / 8, 256>>>(la);

    cudaFuncSetAttribute(gemm_kernel, cudaFuncAttributeMaxDynamicSharedMemorySize,
                         SMEM_GEMM);
    dim3 ggrid(S_ / 128, B_);   // (32, 64) -> 2048 CTAs
    gemm_kernel<<<ggrid, 256, SMEM_GEMM>>>(ls);

    pool_kernel<<<(B_ * A_ * NTASK_) / 8, 256>>>(wg);

    final_kernel<<<1, 256>>>(alpha, out);
}